// round 12
// baseline (speedup 1.0000x reference)
#include <cuda_runtime.h>
#include <math.h>
#include <stdint.h>

#define NNODES 50000
#define NEDGES 400000
#define HEADS 4
#define CH 128
#define KIN 128
#define NOUT (HEADS * CH)          // 512
#define NH (NNODES * HEADS)        // 200000
#define ETOT (NEDGES + NNODES)     // 450000
#define NEG_SLOPE 0.2f
#define MTILES ((NNODES + 63) / 64)     // 782 (M-tile = 64)

// -------- scratch --------
__device__ float g_h[(size_t)NNODES * NOUT];
__device__ float g_xp[(size_t)NNODES * KIN];   // tf32-rounded, k-permuted X
__device__ float g_wtp[(size_t)NOUT * KIN];    // tf32-rounded, transposed, k-permuted W
__device__ float g_asrc[NH];
__device__ float g_adst[NH];
__device__ float g_rden[NH];
__device__ float g_eexp[(size_t)ETOT * HEADS];
__device__ int   g_deg[NNODES];
__device__ int   g_start[NNODES];
__device__ int   g_work[NNODES];
__device__ int   g_csr[ETOT];
__device__ int   g_total;

__device__ __forceinline__ float lrelu(float v) { return v > 0.f ? v : NEG_SLOPE * v; }

__device__ __forceinline__ uint32_t f2tf32(float x) {  // RNE round to tf32
    uint32_t u = __float_as_uint(x);
    uint32_t r = u + 0xFFFu + ((u >> 13) & 1u);
    return r & 0xFFFFE000u;
}

// ------------------------------------------------------------------
// prep: round to tf32 + permute k within 8-groups (pos = 2*(k&3) + (k>>2))
// ------------------------------------------------------------------
#define NXG (NNODES * KIN / 8)     // 800,000 X groups
#define NWG (NOUT * KIN / 8)       // 8,192 W groups
__global__ __launch_bounds__(256) void prep_kernel(const float* __restrict__ X,
                                                   const float* __restrict__ W) {
    const int idx = blockIdx.x * blockDim.x + threadIdx.x;
    if (idx < NXG) {
        const size_t base = (size_t)idx * 8;
        const float4 lo = *(const float4*)&X[base];
        const float4 hi = *(const float4*)&X[base + 4];
        uint4 o0, o1;
        o0.x = f2tf32(lo.x); o0.y = f2tf32(hi.x); o0.z = f2tf32(lo.y); o0.w = f2tf32(hi.y);
        o1.x = f2tf32(lo.z); o1.y = f2tf32(hi.z); o1.z = f2tf32(lo.w); o1.w = f2tf32(hi.w);
        *(uint4*)&g_xp[base] = o0;
        *(uint4*)&g_xp[base + 4] = o1;
    } else if (idx < NXG + NWG) {
        const int w = idx - NXG;
        const int n_glob = w >> 4;          // 0..511
        const int grp = w & 15;             // k-group
        float v[8];
#pragma unroll
        for (int j = 0; j < 8; j++) v[j] = W[(size_t)(grp * 8 + j) * NOUT + n_glob];
        float* op = &g_wtp[(size_t)n_glob * KIN + grp * 8];
        uint4 o0, o1;
        o0.x = f2tf32(v[0]); o0.y = f2tf32(v[4]); o0.z = f2tf32(v[1]); o0.w = f2tf32(v[5]);
        o1.x = f2tf32(v[2]); o1.y = f2tf32(v[6]); o1.z = f2tf32(v[3]); o1.w = f2tf32(v[7]);
        *(uint4*)op = o0;
        *(uint4*)(op + 4) = o1;
    }
    if (idx < NNODES) g_deg[idx] = 0;
    if (idx == 0) g_total = 0;
}

// ==================================================================
// TF32 GEMM via mma.sync (m16n8k8), 64x128 tile, cp.async double
// buffer, 3 CTAs/SM for latency hiding.
// ==================================================================
#define SA_STR 40
#define SB_STR 40
#define SA_CH (64 * SA_STR)         // 2560 floats per buffer
#define SB_CH (128 * SB_STR)        // 5120
#define SMEM_DYN ((2 * SA_CH + 2 * SB_CH) * 4)   // 61440 bytes

__device__ __forceinline__ void mma_tf32(float* c, const uint32_t* a, const uint32_t* b) {
    asm volatile(
        "mma.sync.aligned.m16n8k8.row.col.f32.tf32.tf32.f32 "
        "{%0,%1,%2,%3}, {%4,%5,%6,%7}, {%8,%9}, {%0,%1,%2,%3};"
        : "+f"(c[0]), "+f"(c[1]), "+f"(c[2]), "+f"(c[3])
        : "r"(a[0]), "r"(a[1]), "r"(a[2]), "r"(a[3]), "r"(b[0]), "r"(b[1]));
}

__device__ __forceinline__ void cp16(uint32_t saddr, const void* gptr, uint32_t sz) {
    asm volatile("cp.async.cg.shared.global [%0], [%1], 16, %2;"
                 :: "r"(saddr), "l"(gptr), "r"(sz) : "memory");
}

__global__ __launch_bounds__(256, 3) void gemm_mma_kernel(const float* __restrict__ att_src,
                                                          const float* __restrict__ att_dst) {
    extern __shared__ float dyn[];
    float* sAf = dyn;                 // [2][SA_CH]  A: [m][k_perm], 64 rows
    float* sBf = dyn + 2 * SA_CH;     // [2][SB_CH]  B: [n][k_perm], 128 rows
    __shared__ float s_att[256];
    __shared__ float s_sc[128];       // 64 rows x (s, d)

    const int tid = threadIdx.x;
    const int lane = tid & 31;
    const int wid = tid >> 5;
    const int groupID = lane >> 2;
    const int tid4 = lane & 3;
    const int warp_m = wid & 1;     // 0..1 (32 M rows each)
    const int warp_n = wid >> 1;    // 0..3 (32 N cols each)
    const int bm = blockIdx.x * 64;
    const int head = blockIdx.y;

    if (tid < 128) s_att[tid] = att_src[head * CH + tid];
    else s_att[tid] = att_dst[head * CH + (tid - 128)];
    if (tid < 128) s_sc[tid] = 0.f;

    const uint32_t sA_base = (uint32_t)__cvta_generic_to_shared(sAf);
    const uint32_t sB_base = (uint32_t)__cvta_generic_to_shared(sBf);

    // load chunk kc (32 k) into buffer b
    auto load_chunk = [&](int kc, int b) {
#pragma unroll
        for (int it = 0; it < 2; it++) {     // A: 64 rows x 8 segs = 512 ops
            const int idx = it * 256 + tid;
            const int row = idx >> 3;
            const int seg = idx & 7;
            const uint32_t sz = (bm + row < NNODES) ? 16u : 0u;
            cp16(sA_base + (b * SA_CH + row * SA_STR + seg * 4) * 4,
                 &g_xp[(size_t)(bm + row) * KIN + kc * 32 + seg * 4], sz);
        }
#pragma unroll
        for (int it = 0; it < 4; it++) {     // B: 128 rows x 8 segs = 1024 ops
            const int idx = it * 256 + tid;
            const int row = idx >> 3;
            const int seg = idx & 7;
            cp16(sB_base + (b * SB_CH + row * SB_STR + seg * 4) * 4,
                 &g_wtp[(size_t)(head * 128 + row) * KIN + kc * 32 + seg * 4], 16u);
        }
    };

    float c[2][4][4];
#pragma unroll
    for (int mt = 0; mt < 2; mt++)
#pragma unroll
        for (int nt = 0; nt < 4; nt++)
#pragma unroll
            for (int r = 0; r < 4; r++) c[mt][nt][r] = 0.f;

    load_chunk(0, 0);
    asm volatile("cp.async.commit_group;" ::: "memory");

#pragma unroll 1
    for (int kc = 0; kc < 4; kc++) {
        const int cur = kc & 1;
        if (kc < 3) {
            load_chunk(kc + 1, cur ^ 1);
            asm volatile("cp.async.commit_group;" ::: "memory");
            asm volatile("cp.async.wait_group 1;" ::: "memory");
        } else {
            asm volatile("cp.async.wait_group 0;" ::: "memory");
        }
        __syncthreads();

        const float* sA = sAf + cur * SA_CH;
        const float* sB = sBf + cur * SB_CH;
#pragma unroll
        for (int ks = 0; ks < 4; ks++) {
            const int koff = ks * 8 + 2 * tid4;
            uint32_t a[2][4];
#pragma unroll
            for (int mt = 0; mt < 2; mt++) {
                const int m0 = warp_m * 32 + mt * 16 + groupID;
                const uint2 lo = *(const uint2*)&sA[m0 * SA_STR + koff];
                const uint2 hi = *(const uint2*)&sA[(m0 + 8) * SA_STR + koff];
                a[mt][0] = lo.x; a[mt][1] = hi.x; a[mt][2] = lo.y; a[mt][3] = hi.y;
            }
            uint32_t b[4][2];
#pragma unroll
            for (int nt = 0; nt < 4; nt++) {
                const int n0 = warp_n * 32 + nt * 8 + groupID;
                const uint2 bv = *(const uint2*)&sB[n0 * SB_STR + koff];
                b[nt][0] = bv.x; b[nt][1] = bv.y;
            }
#pragma unroll
            for (int mt = 0; mt < 2; mt++)
#pragma unroll
                for (int nt = 0; nt < 4; nt++) mma_tf32(c[mt][nt], a[mt], b[nt]);
        }
        __syncthreads();
    }

    // ---- epilogue: store h + fused attention scores ----
#pragma unroll
    for (int mt = 0; mt < 2; mt++) {
        const int mloc0 = warp_m * 32 + mt * 16 + groupID;
        const int mloc1 = mloc0 + 8;
        float s0 = 0.f, d0 = 0.f, s1 = 0.f, d1 = 0.f;
#pragma unroll
        for (int nt = 0; nt < 4; nt++) {
            const int col = warp_n * 32 + nt * 8 + 2 * tid4;
            const float sa0 = s_att[col], sa1 = s_att[col + 1];
            const float da0 = s_att[128 + col], da1 = s_att[128 + col + 1];
            s0 = fmaf(c[mt][nt][0], sa0, fmaf(c[mt][nt][1], sa1, s0));
            d0 = fmaf(c[mt][nt][0], da0, fmaf(c[mt][nt][1], da1, d0));
            s1 = fmaf(c[mt][nt][2], sa0, fmaf(c[mt][nt][3], sa1, s1));
            d1 = fmaf(c[mt][nt][2], da0, fmaf(c[mt][nt][3], da1, d1));
        }
#pragma unroll
        for (int o = 1; o <= 2; o <<= 1) {
            s0 += __shfl_xor_sync(0xffffffffu, s0, o);
            d0 += __shfl_xor_sync(0xffffffffu, d0, o);
            s1 += __shfl_xor_sync(0xffffffffu, s1, o);
            d1 += __shfl_xor_sync(0xffffffffu, d1, o);
        }
        if (tid4 == 0) {
            atomicAdd(&s_sc[mloc0 * 2 + 0], s0);
            atomicAdd(&s_sc[mloc0 * 2 + 1], d0);
            atomicAdd(&s_sc[mloc1 * 2 + 0], s1);
            atomicAdd(&s_sc[mloc1 * 2 + 1], d1);
        }
        const int r0 = bm + mloc0;
        const int r1 = bm + mloc1;
#pragma unroll
        for (int nt = 0; nt < 4; nt++) {
            const int col = head * 128 + warp_n * 32 + nt * 8 + 2 * tid4;
            if (r0 < NNODES)
                *(float2*)&g_h[(size_t)r0 * NOUT + col] = make_float2(c[mt][nt][0], c[mt][nt][1]);
            if (r1 < NNODES)
                *(float2*)&g_h[(size_t)r1 * NOUT + col] = make_float2(c[mt][nt][2], c[mt][nt][3]);
        }
    }
    __syncthreads();
    if (tid < 64) {
        const int r = bm + tid;
        if (r < NNODES) {
            g_asrc[r * 4 + head] = s_sc[tid * 2 + 0];
            g_adst[r * 4 + head] = s_sc[tid * 2 + 1];
        }
    }
}

// ------------------------------------------------------------------
// CSR build
// ------------------------------------------------------------------
__global__ __launch_bounds__(256) void hist_kernel(const int* __restrict__ ei) {
    const int e = blockIdx.x * blockDim.x + threadIdx.x;
    if (e >= ETOT) return;
    const int dst = (e < NEDGES) ? ei[NEDGES + e] : (e - NEDGES);
    atomicAdd(&g_deg[dst], 1);
}

__global__ __launch_bounds__(256) void scan_kernel() {
    __shared__ int wsum[8];
    __shared__ int s_base;
    const int tid = threadIdx.x;
    const int lane = tid & 31;
    const int warp = tid >> 5;
    const int i = blockIdx.x * 256 + tid;

    const int d = (i < NNODES) ? g_deg[i] : 0;
    int v = d;
#pragma unroll
    for (int o = 1; o < 32; o <<= 1) {
        int t = __shfl_up_sync(0xffffffffu, v, o);
        if (lane >= o) v += t;
    }
    if (lane == 31) wsum[warp] = v;
    __syncthreads();
    if (tid == 0) {
        int run = 0;
#pragma unroll
        for (int w = 0; w < 8; w++) { int t = wsum[w]; wsum[w] = run; run += t; }
        s_base = atomicAdd(&g_total, run);
    }
    __syncthreads();
    if (i < NNODES) {
        const int excl = s_base + wsum[warp] + v - d;
        g_start[i] = excl;
        g_work[i] = excl;
    }
}

__global__ __launch_bounds__(256) void scatter_kernel(const int* __restrict__ ei) {
    const int e = blockIdx.x * blockDim.x + threadIdx.x;
    if (e >= ETOT) return;
    int src, dst;
    if (e < NEDGES) { src = ei[e]; dst = ei[NEDGES + e]; }
    else { src = dst = e - NEDGES; }
    const int pos = atomicAdd(&g_work[dst], 1);
    g_csr[pos] = src;
}

// ------------------------------------------------------------------
// softmax: one warp per dst node (all 4 heads)
// ------------------------------------------------------------------
__global__ __launch_bounds__(256) void softmax_kernel() {
    const int gw = blockIdx.x * 8 + (threadIdx.x >> 5);
    const int lane = threadIdx.x & 31;
    if (gw >= NNODES) return;

    const int start = g_start[gw];
    const int deg = g_deg[gw];
    const float4 ad = *(const float4*)&g_adst[gw * 4];

    float4 mx = make_float4(-INFINITY, -INFINITY, -INFINITY, -INFINITY);
    for (int i = lane; i < deg; i += 32) {
        const int src = g_csr[start + i];
        const float4 as = *(const float4*)&g_asrc[src * 4];
        mx.x = fmaxf(mx.x, lrelu(as.x + ad.x));
        mx.y = fmaxf(mx.y, lrelu(as.y + ad.y));
        mx.z = fmaxf(mx.z, lrelu(as.z + ad.z));
        mx.w = fmaxf(mx.w, lrelu(as.w + ad.w));
    }
#pragma unroll
    for (int o = 16; o; o >>= 1) {
        mx.x = fmaxf(mx.x, __shfl_xor_sync(0xffffffffu, mx.x, o));
        mx.y = fmaxf(mx.y, __shfl_xor_sync(0xffffffffu, mx.y, o));
        mx.z = fmaxf(mx.z, __shfl_xor_sync(0xffffffffu, mx.z, o));
        mx.w = fmaxf(mx.w, __shfl_xor_sync(0xffffffffu, mx.w, o));
    }

    float4 sm = make_float4(0.f, 0.f, 0.f, 0.f);
    for (int i = lane; i < deg; i += 32) {
        const int src = g_csr[start + i];
        const float4 as = *(const float4*)&g_asrc[src * 4];
        float4 e;
        e.x = __expf(lrelu(as.x + ad.x) - mx.x);
        e.y = __expf(lrelu(as.y + ad.y) - mx.y);
        e.z = __expf(lrelu(as.z + ad.z) - mx.z);
        e.w = __expf(lrelu(as.w + ad.w) - mx.w);
        *(float4*)&g_eexp[(size_t)(start + i) * 4] = e;
        sm.x += e.x; sm.y += e.y; sm.z += e.z; sm.w += e.w;
    }
#pragma unroll
    for (int o = 16; o; o >>= 1) {
        sm.x += __shfl_xor_sync(0xffffffffu, sm.x, o);
        sm.y += __shfl_xor_sync(0xffffffffu, sm.y, o);
        sm.z += __shfl_xor_sync(0xffffffffu, sm.z, o);
        sm.w += __shfl_xor_sync(0xffffffffu, sm.w, o);
    }
    if (lane == 0) {
        float4 r;
        r.x = 1.0f / sm.x; r.y = 1.0f / sm.y; r.z = 1.0f / sm.z; r.w = 1.0f / sm.w;
        *(float4*)&g_rden[gw * 4] = r;
    }
}

// ------------------------------------------------------------------
// aggregation: one warp per (dst, head)
// ------------------------------------------------------------------
__global__ __launch_bounds__(256) void aggregate_kernel(const float* __restrict__ bias,
                                                        float* __restrict__ out) {
    const int gw = blockIdx.x * 8 + (threadIdx.x >> 5);
    const int lane = threadIdx.x & 31;
    if (gw >= NH) return;
    const int dst = gw >> 2;
    const int hd = gw & 3;

    const int start = g_start[dst];
    const int deg = g_deg[dst];
    const float invd = g_rden[dst * 4 + hd];

    float4 acc = make_float4(0.f, 0.f, 0.f, 0.f);
    for (int base = 0; base < deg; base += 32) {
        const int n = min(32, deg - base);
        int src_l = 0;
        float e_l = 0.f;
        if (lane < n) {
            src_l = g_csr[start + base + lane];
            e_l = g_eexp[(size_t)(start + base + lane) * 4 + hd];
        }
        for (int j = 0; j < n; j++) {
            const int src = __shfl_sync(0xffffffffu, src_l, j);
            const float al = __shfl_sync(0xffffffffu, e_l, j) * invd;
            const float4 hv = *(const float4*)&g_h[(size_t)src * NOUT + hd * CH + lane * 4];
            acc.x = fmaf(al, hv.x, acc.x);
            acc.y = fmaf(al, hv.y, acc.y);
            acc.z = fmaf(al, hv.z, acc.z);
            acc.w = fmaf(al, hv.w, acc.w);
        }
    }
    const float4 b = *(const float4*)&bias[hd * CH + lane * 4];
    acc.x += b.x; acc.y += b.y; acc.z += b.z; acc.w += b.w;
    *(float4*)&out[(size_t)dst * NOUT + hd * CH + lane * 4] = acc;
}

// ------------------------------------------------------------------
extern "C" void kernel_launch(void* const* d_in, const int* in_sizes, int n_in,
                              void* d_out, int out_size) {
    const float* x       = (const float*)d_in[0];
    const int* ei        = (const int*)d_in[1];
    const float* W       = (const float*)d_in[2];
    const float* att_src = (const float*)d_in[3];
    const float* att_dst = (const float*)d_in[4];
    const float* bias    = (const float*)d_in[5];
    float* out           = (float*)d_out;

    (void)in_sizes; (void)n_in; (void)out_size;

    cudaFuncSetAttribute(gemm_mma_kernel, cudaFuncAttributeMaxDynamicSharedMemorySize, SMEM_DYN);

    prep_kernel<<<(NXG + NWG + 255) / 256, 256>>>(x, W);
    {
        dim3 grid(MTILES, HEADS);
        gemm_mma_kernel<<<grid, 256, SMEM_DYN>>>(att_src, att_dst);
    }
    hist_kernel<<<(ETOT + 255) / 256, 256>>>(ei);
    scan_kernel<<<(NNODES + 255) / 256, 256>>>();
    scatter_kernel<<<(ETOT + 255) / 256, 256>>>(ei);
    softmax_kernel<<<(NNODES + 7) / 8, 256>>>();
    aggregate_kernel<<<(NH + 7) / 8, 256>>>(bias, out);
}

// round 15
// speedup vs baseline: 1.2821x; 1.2821x over previous
#include <cuda_runtime.h>
#include <cuda_fp16.h>
#include <math.h>
#include <stdint.h>

#define NNODES 50000
#define NEDGES 400000
#define HEADS 4
#define CH 128
#define KIN 128
#define NOUT (HEADS * CH)          // 512
#define NH (NNODES * HEADS)        // 200000
#define ETOT (NEDGES + NNODES)     // 450000
#define NEG_SLOPE 0.2f
#define MTILES ((NNODES + 127) / 128)   // 391

// -------- scratch --------
__device__ __half g_hh[(size_t)NNODES * NOUT];   // h in fp16 (51.2 MB, L2-resident)
__device__ float g_xp[(size_t)NNODES * KIN];     // tf32-rounded, k-permuted X
__device__ float g_wtp[(size_t)NOUT * KIN];      // tf32-rounded, transposed, k-permuted W
__device__ float g_asrc[NH];
__device__ float g_adst[NH];
__device__ float g_rden[NH];
__device__ float g_eexp[(size_t)ETOT * HEADS];
__device__ int   g_deg[NNODES];
__device__ int   g_start[NNODES];
__device__ int   g_work[NNODES];
__device__ int   g_csr[ETOT];
__device__ int   g_total;

__device__ __forceinline__ float lrelu(float v) { return v > 0.f ? v : NEG_SLOPE * v; }

__device__ __forceinline__ uint32_t f2tf32(float x) {  // RNE round to tf32
    uint32_t u = __float_as_uint(x);
    uint32_t r = u + 0xFFFu + ((u >> 13) & 1u);
    return r & 0xFFFFE000u;
}

// ------------------------------------------------------------------
// prep: round to tf32 + permute k within 8-groups (pos = 2*(k&3) + (k>>2))
// ------------------------------------------------------------------
#define NXG (NNODES * KIN / 8)     // 800,000 X groups
#define NWG (NOUT * KIN / 8)       // 8,192 W groups
__global__ __launch_bounds__(256) void prep_kernel(const float* __restrict__ X,
                                                   const float* __restrict__ W) {
    const int idx = blockIdx.x * blockDim.x + threadIdx.x;
    if (idx < NXG) {
        const size_t base = (size_t)idx * 8;
        const float4 lo = *(const float4*)&X[base];
        const float4 hi = *(const float4*)&X[base + 4];
        uint4 o0, o1;
        o0.x = f2tf32(lo.x); o0.y = f2tf32(hi.x); o0.z = f2tf32(lo.y); o0.w = f2tf32(hi.y);
        o1.x = f2tf32(lo.z); o1.y = f2tf32(hi.z); o1.z = f2tf32(lo.w); o1.w = f2tf32(hi.w);
        *(uint4*)&g_xp[base] = o0;
        *(uint4*)&g_xp[base + 4] = o1;
    } else if (idx < NXG + NWG) {
        const int w = idx - NXG;
        const int n_glob = w >> 4;          // 0..511
        const int grp = w & 15;             // k-group
        float v[8];
#pragma unroll
        for (int j = 0; j < 8; j++) v[j] = W[(size_t)(grp * 8 + j) * NOUT + n_glob];
        float* op = &g_wtp[(size_t)n_glob * KIN + grp * 8];
        uint4 o0, o1;
        o0.x = f2tf32(v[0]); o0.y = f2tf32(v[4]); o0.z = f2tf32(v[1]); o0.w = f2tf32(v[5]);
        o1.x = f2tf32(v[2]); o1.y = f2tf32(v[6]); o1.z = f2tf32(v[3]); o1.w = f2tf32(v[7]);
        *(uint4*)op = o0;
        *(uint4*)(op + 4) = o1;
    }
    if (idx < NNODES) g_deg[idx] = 0;
    if (idx == 0) g_total = 0;
}

// ==================================================================
// TF32 GEMM via mma.sync (m16n8k8), 128x128 tile (R11 config),
// cp.async double buffer, LDS.64 fragment loads, fp16 h output.
// ==================================================================
#define SA_STR 40
#define SB_STR 40
#define SA_CH (128 * SA_STR)        // 5120 floats per buffer
#define SB_CH (128 * SB_STR)        // 5120
#define SMEM_DYN ((2 * SA_CH + 2 * SB_CH) * 4)   // 81920 bytes

__device__ __forceinline__ void mma_tf32(float* c, const uint32_t* a, const uint32_t* b) {
    asm volatile(
        "mma.sync.aligned.m16n8k8.row.col.f32.tf32.tf32.f32 "
        "{%0,%1,%2,%3}, {%4,%5,%6,%7}, {%8,%9}, {%0,%1,%2,%3};"
        : "+f"(c[0]), "+f"(c[1]), "+f"(c[2]), "+f"(c[3])
        : "r"(a[0]), "r"(a[1]), "r"(a[2]), "r"(a[3]), "r"(b[0]), "r"(b[1]));
}

__device__ __forceinline__ void cp16(uint32_t saddr, const void* gptr, uint32_t sz) {
    asm volatile("cp.async.cg.shared.global [%0], [%1], 16, %2;"
                 :: "r"(saddr), "l"(gptr), "r"(sz) : "memory");
}

__global__ __launch_bounds__(256, 2) void gemm_mma_kernel(const float* __restrict__ att_src,
                                                          const float* __restrict__ att_dst) {
    extern __shared__ float dyn[];
    float* sAf = dyn;                 // [2][SA_CH]  A: [m][k_perm]
    float* sBf = dyn + 2 * SA_CH;     // [2][SB_CH]  B: [n][k_perm]
    __shared__ float s_att[256];
    __shared__ float s_sc[256];

    const int tid = threadIdx.x;
    const int lane = tid & 31;
    const int wid = tid >> 5;
    const int groupID = lane >> 2;
    const int tid4 = lane & 3;
    const int warp_m = wid >> 2;    // 0..1
    const int warp_n = wid & 3;     // 0..3
    const int bm = blockIdx.x * 128;
    const int head = blockIdx.y;

    if (tid < 128) s_att[tid] = att_src[head * CH + tid];
    else s_att[tid] = att_dst[head * CH + (tid - 128)];
    s_sc[tid] = 0.f;

    const uint32_t sA_base = (uint32_t)__cvta_generic_to_shared(sAf);
    const uint32_t sB_base = (uint32_t)__cvta_generic_to_shared(sBf);

    auto load_chunk = [&](int kc, int b) {
#pragma unroll
        for (int it = 0; it < 4; it++) {
            const int idx = it * 256 + tid;
            const int row = idx >> 3;
            const int seg = idx & 7;
            const uint32_t sz = (bm + row < NNODES) ? 16u : 0u;
            cp16(sA_base + (b * SA_CH + row * SA_STR + seg * 4) * 4,
                 &g_xp[(size_t)(bm + row) * KIN + kc * 32 + seg * 4], sz);
        }
#pragma unroll
        for (int it = 0; it < 4; it++) {
            const int idx = it * 256 + tid;
            const int row = idx >> 3;
            const int seg = idx & 7;
            cp16(sB_base + (b * SB_CH + row * SB_STR + seg * 4) * 4,
                 &g_wtp[(size_t)(head * 128 + row) * KIN + kc * 32 + seg * 4], 16u);
        }
    };

    float c[4][4][4];
#pragma unroll
    for (int mt = 0; mt < 4; mt++)
#pragma unroll
        for (int nt = 0; nt < 4; nt++)
#pragma unroll
            for (int r = 0; r < 4; r++) c[mt][nt][r] = 0.f;

    load_chunk(0, 0);
    asm volatile("cp.async.commit_group;" ::: "memory");

#pragma unroll 1
    for (int kc = 0; kc < 4; kc++) {
        const int cur = kc & 1;
        if (kc < 3) {
            load_chunk(kc + 1, cur ^ 1);
            asm volatile("cp.async.commit_group;" ::: "memory");
            asm volatile("cp.async.wait_group 1;" ::: "memory");
        } else {
            asm volatile("cp.async.wait_group 0;" ::: "memory");
        }
        __syncthreads();

        const float* sA = sAf + cur * SA_CH;
        const float* sB = sBf + cur * SB_CH;
#pragma unroll
        for (int ks = 0; ks < 4; ks++) {
            const int koff = ks * 8 + 2 * tid4;
            uint32_t a[4][4];
#pragma unroll
            for (int mt = 0; mt < 4; mt++) {
                const int m0 = warp_m * 64 + mt * 16 + groupID;
                const uint2 lo = *(const uint2*)&sA[m0 * SA_STR + koff];
                const uint2 hi = *(const uint2*)&sA[(m0 + 8) * SA_STR + koff];
                a[mt][0] = lo.x; a[mt][1] = hi.x; a[mt][2] = lo.y; a[mt][3] = hi.y;
            }
            uint32_t b[4][2];
#pragma unroll
            for (int nt = 0; nt < 4; nt++) {
                const int n0 = warp_n * 32 + nt * 8 + groupID;
                const uint2 bv = *(const uint2*)&sB[n0 * SB_STR + koff];
                b[nt][0] = bv.x; b[nt][1] = bv.y;
            }
#pragma unroll
            for (int mt = 0; mt < 4; mt++)
#pragma unroll
                for (int nt = 0; nt < 4; nt++) mma_tf32(c[mt][nt], a[mt], b[nt]);
        }
        __syncthreads();
    }

    // ---- epilogue: store h (fp16) + fused attention scores (fp32) ----
#pragma unroll
    for (int mt = 0; mt < 4; mt++) {
        const int mloc0 = warp_m * 64 + mt * 16 + groupID;
        const int mloc1 = mloc0 + 8;
        float s0 = 0.f, d0 = 0.f, s1 = 0.f, d1 = 0.f;
#pragma unroll
        for (int nt = 0; nt < 4; nt++) {
            const int col = warp_n * 32 + nt * 8 + 2 * tid4;
            const float sa0 = s_att[col], sa1 = s_att[col + 1];
            const float da0 = s_att[128 + col], da1 = s_att[128 + col + 1];
            s0 = fmaf(c[mt][nt][0], sa0, fmaf(c[mt][nt][1], sa1, s0));
            d0 = fmaf(c[mt][nt][0], da0, fmaf(c[mt][nt][1], da1, d0));
            s1 = fmaf(c[mt][nt][2], sa0, fmaf(c[mt][nt][3], sa1, s1));
            d1 = fmaf(c[mt][nt][2], da0, fmaf(c[mt][nt][3], da1, d1));
        }
#pragma unroll
        for (int o = 1; o <= 2; o <<= 1) {
            s0 += __shfl_xor_sync(0xffffffffu, s0, o);
            d0 += __shfl_xor_sync(0xffffffffu, d0, o);
            s1 += __shfl_xor_sync(0xffffffffu, s1, o);
            d1 += __shfl_xor_sync(0xffffffffu, d1, o);
        }
        if (tid4 == 0) {
            atomicAdd(&s_sc[mloc0 * 2 + 0], s0);
            atomicAdd(&s_sc[mloc0 * 2 + 1], d0);
            atomicAdd(&s_sc[mloc1 * 2 + 0], s1);
            atomicAdd(&s_sc[mloc1 * 2 + 1], d1);
        }
        const int r0 = bm + mloc0;
        const int r1 = bm + mloc1;
#pragma unroll
        for (int nt = 0; nt < 4; nt++) {
            const int col = head * 128 + warp_n * 32 + nt * 8 + 2 * tid4;
            if (r0 < NNODES)
                *(__half2*)&g_hh[(size_t)r0 * NOUT + col] = __floats2half2_rn(c[mt][nt][0], c[mt][nt][1]);
            if (r1 < NNODES)
                *(__half2*)&g_hh[(size_t)r1 * NOUT + col] = __floats2half2_rn(c[mt][nt][2], c[mt][nt][3]);
        }
    }
    __syncthreads();
    if (tid < 128) {
        const int r = bm + tid;
        if (r < NNODES) {
            g_asrc[r * 4 + head] = s_sc[tid * 2 + 0];
            g_adst[r * 4 + head] = s_sc[tid * 2 + 1];
        }
    }
}

// ------------------------------------------------------------------
// CSR build
// ------------------------------------------------------------------
__global__ __launch_bounds__(256) void hist_kernel(const int* __restrict__ ei) {
    const int e = blockIdx.x * blockDim.x + threadIdx.x;
    if (e >= ETOT) return;
    const int dst = (e < NEDGES) ? ei[NEDGES + e] : (e - NEDGES);
    atomicAdd(&g_deg[dst], 1);
}

__global__ __launch_bounds__(256) void scan_kernel() {
    __shared__ int wsum[8];
    __shared__ int s_base;
    const int tid = threadIdx.x;
    const int lane = tid & 31;
    const int warp = tid >> 5;
    const int i = blockIdx.x * 256 + tid;

    const int d = (i < NNODES) ? g_deg[i] : 0;
    int v = d;
#pragma unroll
    for (int o = 1; o < 32; o <<= 1) {
        int t = __shfl_up_sync(0xffffffffu, v, o);
        if (lane >= o) v += t;
    }
    if (lane == 31) wsum[warp] = v;
    __syncthreads();
    if (tid == 0) {
        int run = 0;
#pragma unroll
        for (int w = 0; w < 8; w++) { int t = wsum[w]; wsum[w] = run; run += t; }
        s_base = atomicAdd(&g_total, run);
    }
    __syncthreads();
    if (i < NNODES) {
        const int excl = s_base + wsum[warp] + v - d;
        g_start[i] = excl;
        g_work[i] = excl;
    }
}

__global__ __launch_bounds__(256) void scatter_kernel(const int* __restrict__ ei) {
    const int e = blockIdx.x * blockDim.x + threadIdx.x;
    if (e >= ETOT) return;
    int src, dst;
    if (e < NEDGES) { src = ei[e]; dst = ei[NEDGES + e]; }
    else { src = dst = e - NEDGES; }
    const int pos = atomicAdd(&g_work[dst], 1);
    g_csr[pos] = src;
}

// ------------------------------------------------------------------
// softmax: one warp per dst node (all 4 heads)
// ------------------------------------------------------------------
__global__ __launch_bounds__(256) void softmax_kernel() {
    const int gw = blockIdx.x * 8 + (threadIdx.x >> 5);
    const int lane = threadIdx.x & 31;
    if (gw >= NNODES) return;

    const int start = g_start[gw];
    const int deg = g_deg[gw];
    const float4 ad = *(const float4*)&g_adst[gw * 4];

    float4 mx = make_float4(-INFINITY, -INFINITY, -INFINITY, -INFINITY);
    for (int i = lane; i < deg; i += 32) {
        const int src = g_csr[start + i];
        const float4 as = *(const float4*)&g_asrc[src * 4];
        mx.x = fmaxf(mx.x, lrelu(as.x + ad.x));
        mx.y = fmaxf(mx.y, lrelu(as.y + ad.y));
        mx.z = fmaxf(mx.z, lrelu(as.z + ad.z));
        mx.w = fmaxf(mx.w, lrelu(as.w + ad.w));
    }
#pragma unroll
    for (int o = 16; o; o >>= 1) {
        mx.x = fmaxf(mx.x, __shfl_xor_sync(0xffffffffu, mx.x, o));
        mx.y = fmaxf(mx.y, __shfl_xor_sync(0xffffffffu, mx.y, o));
        mx.z = fmaxf(mx.z, __shfl_xor_sync(0xffffffffu, mx.z, o));
        mx.w = fmaxf(mx.w, __shfl_xor_sync(0xffffffffu, mx.w, o));
    }

    float4 sm = make_float4(0.f, 0.f, 0.f, 0.f);
    for (int i = lane; i < deg; i += 32) {
        const int src = g_csr[start + i];
        const float4 as = *(const float4*)&g_asrc[src * 4];
        float4 e;
        e.x = __expf(lrelu(as.x + ad.x) - mx.x);
        e.y = __expf(lrelu(as.y + ad.y) - mx.y);
        e.z = __expf(lrelu(as.z + ad.z) - mx.z);
        e.w = __expf(lrelu(as.w + ad.w) - mx.w);
        *(float4*)&g_eexp[(size_t)(start + i) * 4] = e;
        sm.x += e.x; sm.y += e.y; sm.z += e.z; sm.w += e.w;
    }
#pragma unroll
    for (int o = 16; o; o >>= 1) {
        sm.x += __shfl_xor_sync(0xffffffffu, sm.x, o);
        sm.y += __shfl_xor_sync(0xffffffffu, sm.y, o);
        sm.z += __shfl_xor_sync(0xffffffffu, sm.z, o);
        sm.w += __shfl_xor_sync(0xffffffffu, sm.w, o);
    }
    if (lane == 0) {
        float4 r;
        r.x = 1.0f / sm.x; r.y = 1.0f / sm.y; r.z = 1.0f / sm.z; r.w = 1.0f / sm.w;
        *(float4*)&g_rden[gw * 4] = r;
    }
}

// ------------------------------------------------------------------
// aggregation: one warp per (dst, head); h rows gathered as fp16
// ------------------------------------------------------------------
__global__ __launch_bounds__(256) void aggregate_kernel(const float* __restrict__ bias,
                                                        float* __restrict__ out) {
    const int gw = blockIdx.x * 8 + (threadIdx.x >> 5);
    const int lane = threadIdx.x & 31;
    if (gw >= NH) return;
    const int dst = gw >> 2;
    const int hd = gw & 3;

    const int start = g_start[dst];
    const int deg = g_deg[dst];
    const float invd = g_rden[dst * 4 + hd];

    float4 acc = make_float4(0.f, 0.f, 0.f, 0.f);
    for (int base = 0; base < deg; base += 32) {
        const int n = min(32, deg - base);
        int src_l = 0;
        float e_l = 0.f;
        if (lane < n) {
            src_l = g_csr[start + base + lane];
            e_l = g_eexp[(size_t)(start + base + lane) * 4 + hd];
        }
        for (int j = 0; j < n; j++) {
            const int src = __shfl_sync(0xffffffffu, src_l, j);
            const float al = __shfl_sync(0xffffffffu, e_l, j) * invd;
            const uint2 hv = *(const uint2*)&g_hh[(size_t)src * NOUT + hd * CH + lane * 4];
            const float2 h01 = __half22float2(*(const __half2*)&hv.x);
            const float2 h23 = __half22float2(*(const __half2*)&hv.y);
            acc.x = fmaf(al, h01.x, acc.x);
            acc.y = fmaf(al, h01.y, acc.y);
            acc.z = fmaf(al, h23.x, acc.z);
            acc.w = fmaf(al, h23.y, acc.w);
        }
    }
    const float4 b = *(const float4*)&bias[hd * CH + lane * 4];
    acc.x += b.x; acc.y += b.y; acc.z += b.z; acc.w += b.w;
    *(float4*)&out[(size_t)dst * NOUT + hd * CH + lane * 4] = acc;
}

// ------------------------------------------------------------------
extern "C" void kernel_launch(void* const* d_in, const int* in_sizes, int n_in,
                              void* d_out, int out_size) {
    const float* x       = (const float*)d_in[0];
    const int* ei        = (const int*)d_in[1];
    const float* W       = (const float*)d_in[2];
    const float* att_src = (const float*)d_in[3];
    const float* att_dst = (const float*)d_in[4];
    const float* bias    = (const float*)d_in[5];
    float* out           = (float*)d_out;

    (void)in_sizes; (void)n_in; (void)out_size;

    cudaFuncSetAttribute(gemm_mma_kernel, cudaFuncAttributeMaxDynamicSharedMemorySize, SMEM_DYN);

    prep_kernel<<<(NXG + NWG + 255) / 256, 256>>>(x, W);
    {
        dim3 grid(MTILES, HEADS);
        gemm_mma_kernel<<<grid, 256, SMEM_DYN>>>(att_src, att_dst);
    }
    hist_kernel<<<(ETOT + 255) / 256, 256>>>(ei);
    scan_kernel<<<(NNODES + 255) / 256, 256>>>();
    scatter_kernel<<<(ETOT + 255) / 256, 256>>>(ei);
    softmax_kernel<<<(NNODES + 7) / 8, 256>>>();
    aggregate_kernel<<<(NH + 7) / 8, 256>>>(bias, out);
}